// round 10
// baseline (speedup 1.0000x reference)
#include <cuda_runtime.h>
#include <stdint.h>

// Shapes (fixed by the problem)
#define B    8
#define C    256
#define HIN  64          // input spatial 64x64
#define S    (HIN*HIN)   // 4096
#define HO   256         // output spatial 256x256
#define K    21
#define EPSF 1e-6f

#define SPLIT  16        // s-range splits (4 y-rows per block)
#define CSPLIT 2         // channel splits (128 c per block) -> 2 CTA/SM
#define SRANGE (S/SPLIT) // 256 s per block
#define SCH    64        // s per feats smem chunk
#define NCH    (SRANGE/SCH)
#define FSTR   68        // padded row stride (floats): 272B, conflict-free float4
#define CB     (C/CSPLIT)

// smem layout (bytes):
//   [0, 43008)              Ws  : resident W dup-pairs [K][SRANGE] u64
//   [43008, 112640)         Fs  : feats double buffer [2][CB*FSTR] f32
//   prologue aliases into the Fs region:
//     T16 at 43008, 49152 B  ([4][HO][6] u64)   dead after P2
//     Cs  at 92160, 11424 B  ([4][K][68] u16)   dead after P3
#define WS_BYTES  (K*SRANGE*8)            // 43008
#define FS_OFF    WS_BYTES
#define FS_BYTES  (CB*FSTR*4)             // 34816 per buffer
#define T16_OFF   FS_OFF                  // 43008
#define CS_OFF    (T16_OFF + 4*HO*6*8)    // 92160
#define SMEM_D    (WS_BYTES + 2*FS_BYTES) // 112640 B -> 2 CTA/SM

// ---------------- scratch (__device__ globals; no allocations) ----------------
__device__ unsigned g_rowcnt[B * K * HIN];        // exact 64*count per (b,k,y) row
__device__ float    g_sums[SPLIT * B * K * C];    // partial per-image per-class sums

// bilinear gather weight (in 1/8 units) of input index r from output index Yx
__device__ __forceinline__ int bil_w8(int Yx, int r) {
    int t  = 2 * Yx - 3;
    int y0 = ((t + 8) >> 3) - 1;
    int f8 = (t + 8) & 7;
    int y0c = min(max(y0, 0), HIN - 1);
    int y1c = min(max(y0 + 1, 0), HIN - 1);
    int w = 0;
    if (y0c == r) w += 8 - f8;
    if (y1c == r) w += f8;
    return w;
}

// packed f32x2 helpers (sm_103a FFMA2 via PTX)
__device__ __forceinline__ void fma2(uint64_t& d, uint64_t a, uint64_t b) {
    asm("fma.rn.f32x2 %0, %1, %2, %0;" : "+l"(d) : "l"(a), "l"(b));
}
__device__ __forceinline__ uint64_t add2(uint64_t a, uint64_t b) {
    uint64_t d; asm("add.rn.f32x2 %0, %1, %2;" : "=l"(d) : "l"(a), "l"(b)); return d;
}
__device__ __forceinline__ uint64_t pack2(float x, float y) {
    uint64_t r; asm("mov.b64 %0, {%1, %2};" : "=l"(r) : "f"(x), "f"(y)); return r;
}
__device__ __forceinline__ void unpack2(float& x, float& y, uint64_t a) {
    asm("mov.b64 {%0, %1}, %2;" : "=f"(x), "=f"(y) : "l"(a));
}
// expand 4 bytes -> 4x 16-bit lanes of a u64
__device__ __forceinline__ uint64_t exp16(unsigned v) {
    return (uint64_t)(v & 0xFFu) | ((uint64_t)(v & 0xFF00u) << 8)
         | ((uint64_t)(v & 0xFF0000u) << 16) | ((uint64_t)(v & 0xFF000000u) << 24);
}
// cp.async 16B
__device__ __forceinline__ void cp16(void* dst, const void* src) {
    unsigned u = (unsigned)__cvta_generic_to_shared(dst);
    asm volatile("cp.async.cg.shared.global [%0], [%1], 16;" :: "r"(u), "l"(src));
}

// ---------------- Kernel D (fused): masks -> W (smem) -> sums ----------------
// grid (SPLIT, CSPLIT, B), block 256. Prologue builds this block's W tile
// (K x 256 s, dup (w,w) pairs) in smem from 16 mask rows via the exact integer
// SIMD16 pipeline; mainloop double-buffers feats via cp.async and contracts
// with warp-uniform broadcast W reads + packed fma.rn.f32x2.
extern "C" __global__ void __launch_bounds__(256, 2) kernD(
        const float* __restrict__ feats, const int* __restrict__ masks) {
    extern __shared__ unsigned char smem[];
    uint64_t* Ws  = (uint64_t*)smem;                 // [K][SRANGE]
    float*    Fs  = (float*)(smem + FS_OFF);         // [2][CB*FSTR]
    uint64_t* T16 = (uint64_t*)(smem + T16_OFF);     // [4][HO][6]
    uint16_t* Cs  = (uint16_t*)(smem + CS_OFF);      // [4][K][68]

    int split = blockIdx.x, cb = blockIdx.y, b = blockIdx.z;
    int tid = threadIdx.x, warp = tid >> 5, lane = tid & 31;
    int g = warp & 1, sub = warp >> 1;               // 2 cgroups x 4 s-subranges

    // ---- Prologue P1: row-downsample 4 y-rows of one-hot masks (X = tid) ----
    #pragma unroll
    for (int yy = 0; yy < 4; yy++) {
        int y = split * 4 + yy;
        uint64_t a0 = 0, a1 = 0, a2 = 0;
        #pragma unroll
        for (int dy = 0; dy < 8; dy++) {
            int Y = 4 * y - 2 + dy;
            if (Y < 0 || Y >= HO) continue;
            int w = bil_w8(Y, y);
            if (w == 0) continue;
            int lbl = masks[(b * HO + Y) * HO + tid];
            if ((unsigned)lbl < (unsigned)K) {
                uint64_t add = (uint64_t)w << ((lbl & 7) * 8);
                int sel = lbl >> 3;
                if (sel == 0)      a0 += add;
                else if (sel == 1) a1 += add;
                else               a2 += add;
            }
        }
        uint64_t* Tp = &T16[(yy * HO + tid) * 6];
        Tp[0] = exp16((unsigned)a0); Tp[1] = exp16((unsigned)(a0 >> 32));
        Tp[2] = exp16((unsigned)a1); Tp[3] = exp16((unsigned)(a1 >> 32));
        Tp[4] = exp16((unsigned)a2); Tp[5] = exp16((unsigned)(a2 >> 32));
    }
    __syncthreads();

    // ---- Prologue P2: column pass (x = tid&63, yy = tid>>6), SIMD16 ---------
    {
        int x = tid & 63, yy = tid >> 6;
        uint64_t acc6[6] = {0, 0, 0, 0, 0, 0};
        #pragma unroll
        for (int dx = 0; dx < 8; dx++) {
            int X = 4 * x - 2 + dx;
            if (X < 0 || X >= HO) continue;
            uint64_t w = (uint64_t)(unsigned)bil_w8(X, x);
            if (w == 0) continue;
            const uint64_t* Tp = &T16[(yy * HO + X) * 6];
            #pragma unroll
            for (int j = 0; j < 6; j++) acc6[j] += Tp[j] * w;
        }
        int sl = yy * HIN + x;     // local s within SRANGE
        #pragma unroll
        for (int k = 0; k < K; k++) {
            unsigned val = (unsigned)((acc6[k >> 2] >> ((k & 3) * 16)) & 0xFFFFull);
            float f = (float)val * (1.0f / 64.0f);
            Ws[k * SRANGE + sl] = pack2(f, f);
            Cs[(yy * K + k) * 68 + x] = (uint16_t)val;
        }
    }
    __syncthreads();   // T16 dead; Ws/Cs valid

    const float* Fg = feats + ((size_t)b * C + cb * CB) * S;
    const int sbase0 = split * SRANGE;

    // kick first feats stage (targets Fs buf0, aliases dead T16 region)
    #define STAGE(BUF, SB) do {                                                   \
        for (int i = tid; i < CB * SCH / 4; i += 256) {                           \
            int c = i >> 4, j4 = i & 15;                                          \
            cp16(&Fs[(BUF) * CB * FSTR + c * FSTR + j4 * 4],                      \
                 Fg + (size_t)c * S + (SB) + j4 * 4);                             \
        }                                                                         \
        asm volatile("cp.async.commit_group;");                                   \
    } while (0)

    STAGE(0, sbase0);

    // ---- Prologue P3 (concurrent with stage 0): exact integer row counts ----
    if (cb == 0 && tid < 4 * K) {
        int yy = tid & 3, k = tid >> 2;
        const uint16_t* cp = &Cs[(yy * K + k) * 68];
        unsigned t = 0;
        #pragma unroll 16
        for (int xx = 0; xx < HIN; xx++) t += (unsigned)cp[xx];
        g_rowcnt[(b * K + k) * HIN + split * 4 + yy] = t;
    }
    __syncthreads();   // Cs dead; buf1 free for prefetch

    uint64_t acc[K];
    #pragma unroll
    for (int k = 0; k < K; k++) acc[k] = 0ull;

    #pragma unroll 1
    for (int chunk = 0; chunk < NCH; chunk++) {
        if (chunk + 1 < NCH) {
            STAGE((chunk + 1) & 1, sbase0 + (chunk + 1) * SCH);
            asm volatile("cp.async.wait_group 1;");
        } else {
            asm volatile("cp.async.wait_group 0;");
        }
        __syncthreads();

        const float* fA = &Fs[(chunk & 1) * CB * FSTR + (g * 32 + lane) * FSTR];
        const float* fB = fA + 64 * FSTR;
        const uint64_t* Wb = &Ws[chunk * SCH];   // + k*SRANGE below
        int sb = sub * 16;
        #pragma unroll
        for (int i = 0; i < 16; i += 4) {
            int s = sb + i;
            float4 va = *(const float4*)&fA[s];
            float4 vb = *(const float4*)&fB[s];
            uint64_t p0 = pack2(va.x, vb.x);
            uint64_t p1 = pack2(va.y, vb.y);
            uint64_t p2 = pack2(va.z, vb.z);
            uint64_t p3 = pack2(va.w, vb.w);
            #pragma unroll
            for (int k = 0; k < K; k++) {
                ulonglong2 w01 = *(const ulonglong2*)&Wb[k * SRANGE + s];       // broadcast
                ulonglong2 w23 = *(const ulonglong2*)&Wb[k * SRANGE + s + 2];   // broadcast
                fma2(acc[k], p0, w01.x);
                fma2(acc[k], p1, w01.y);
                fma2(acc[k], p2, w23.x);
                fma2(acc[k], p3, w23.y);
            }
        }
        __syncthreads();   // protect feats buffer reuse by next prefetch
    }
    #undef STAGE

    // reduce 4 s-subrange warps per channel-group via smem (Ws region, now dead)
    uint64_t* red = (uint64_t*)smem;   // 2g x 2 x K x 32 u64 = 21504 B
    if (sub >= 2) {
        #pragma unroll
        for (int k = 0; k < K; k++) red[((g * 2 + (sub - 2)) * K + k) * 32 + lane] = acc[k];
    }
    __syncthreads();
    if (sub < 2) {
        #pragma unroll
        for (int k = 0; k < K; k++) acc[k] = add2(acc[k], red[((g * 2 + sub) * K + k) * 32 + lane]);
    }
    __syncthreads();
    if (sub == 1) {
        #pragma unroll
        for (int k = 0; k < K; k++) red[(g * K + k) * 32 + lane] = acc[k];
    }
    __syncthreads();
    if (sub == 0) {
        float* outp = &g_sums[(((size_t)split * B + b) * K) * C];
        int cg = cb * CB + g * 32 + lane;
        #pragma unroll
        for (int k = 0; k < K; k++) {
            uint64_t t = add2(acc[k], red[(g * K + k) * 32 + lane]);
            float ax, ay;
            unpack2(ax, ay, t);
            outp[k * C + cg]      = ax;
            outp[k * C + cg + 64] = ay;
        }
    }
}

// ---------------- Kernel E: finalize prototypes ------------------------------
// grid (K, 2), block 256 = 8 warps (one per b) x 32 lanes (float4 of channels)
__global__ void kernE(float* __restrict__ out) {
    int k = blockIdx.x, cg = blockIdx.y;
    int tid = threadIdx.x, b = tid >> 5, lane = tid & 31;
    int c4 = cg * 32 + lane;

    const float4* Sp = (const float4*)g_sums;
    float4 v = make_float4(0.f, 0.f, 0.f, 0.f);
    #pragma unroll
    for (int sp = 0; sp < SPLIT; sp++) {
        float4 t = Sp[((sp * B + b) * K + k) * (C / 4) + c4];
        v.x += t.x; v.y += t.y; v.z += t.z; v.w += t.w;
    }
    const unsigned* rc = &g_rowcnt[(b * K + k) * HIN];
    unsigned cr = rc[lane] + rc[lane + 32];
    #pragma unroll
    for (int o = 16; o > 0; o >>= 1) cr += __shfl_xor_sync(0xFFFFFFFFu, cr, o);
    float inv = 1.0f / ((float)cr * (1.0f / 64.0f) + EPSF);
    v.x *= inv; v.y *= inv; v.z *= inv; v.w *= inv;

    __shared__ float4 red[B][32];
    red[b][lane] = v;
    __syncthreads();
    if (b == 0) {
        float4 a = red[0][lane];
        #pragma unroll
        for (int w = 1; w < B; w++) {
            float4 t = red[w][lane];
            a.x += t.x; a.y += t.y; a.z += t.z; a.w += t.w;
        }
        float sc = 1.0f / (float)B;
        a.x *= sc; a.y *= sc; a.z *= sc; a.w *= sc;
        ((float4*)out)[k * (C / 4) + c4] = a;
    }
}

// ---------------- launch -----------------------------------------------------
extern "C" void kernel_launch(void* const* d_in, const int* in_sizes, int n_in,
                              void* d_out, int out_size) {
    const float* feats = (const float*)d_in[0];   // [8,256,64,64]
    const int*   masks = (const int*)d_in[1];     // [8,256,256]
    float*       out   = (float*)d_out;           // [21,256]

    cudaFuncSetAttribute(kernD, cudaFuncAttributeMaxDynamicSharedMemorySize, SMEM_D);

    kernD<<<dim3(SPLIT, CSPLIT, B), 256, SMEM_D>>>(feats, masks);
    kernE<<<dim3(K, 2), 256>>>(out);
}

// round 12
// speedup vs baseline: 1.1059x; 1.1059x over previous
#include <cuda_runtime.h>
#include <stdint.h>

// Shapes (fixed by the problem)
#define B    8
#define C    256
#define HIN  64          // input spatial 64x64
#define S    (HIN*HIN)   // 4096
#define HO   256         // output spatial 256x256
#define K    21
#define EPSF 1e-6f

#define SPLIT  16        // s-range splits (4 y-rows per block)
#define CSPLIT 2         // channel splits (128 c per block) -> 2 CTA/SM
#define SRANGE (S/SPLIT) // 256 s per block
#define SCH    64        // s per feats smem chunk
#define NCH    (SRANGE/SCH)
#define FSTR   68        // padded row stride (floats): 272B, conflict-free float4
#define CB     (C/CSPLIT)

// smem layout (bytes):
//   [0, 43008)          Ws : resident W dup-pairs [K][SRANGE] u64
//   [43008, 112640)     Fs : feats double buffer [2][CB*FSTR] f32
//   Cs ([4][K][68] u16, 11424 B) aliases the buf1 region (offset 77824),
//   read by P3 while stage0 fills buf0; dead before stage1 overwrites buf1.
#define WS_BYTES  (K*SRANGE*8)            // 43008
#define FS_OFF    WS_BYTES
#define FS_BYTES  (CB*FSTR*4)             // 34816 per buffer
#define CS_OFF    (FS_OFF + FS_BYTES)     // 77824 (buf1 start)
#define SMEM_D    (WS_BYTES + 2*FS_BYTES) // 112640 B -> 2 CTA/SM

// ---------------- scratch (__device__ globals; no allocations) ----------------
__device__ unsigned g_rowcnt[B * K * HIN];        // exact 64*count per (b,k,y) row
__device__ float    g_sums[SPLIT * B * K * C];    // partial per-image per-class sums

// bilinear gather weight (in 1/8 units) of input index r from output index Yx
__device__ __forceinline__ int bil_w8(int Yx, int r) {
    int t  = 2 * Yx - 3;
    int y0 = ((t + 8) >> 3) - 1;
    int f8 = (t + 8) & 7;
    int y0c = min(max(y0, 0), HIN - 1);
    int y1c = min(max(y0 + 1, 0), HIN - 1);
    int w = 0;
    if (y0c == r) w += 8 - f8;
    if (y1c == r) w += f8;
    return w;
}

// packed f32x2 helpers (sm_103a FFMA2 via PTX)
__device__ __forceinline__ void fma2(uint64_t& d, uint64_t a, uint64_t b) {
    asm("fma.rn.f32x2 %0, %1, %2, %0;" : "+l"(d) : "l"(a), "l"(b));
}
__device__ __forceinline__ uint64_t add2(uint64_t a, uint64_t b) {
    uint64_t d; asm("add.rn.f32x2 %0, %1, %2;" : "=l"(d) : "l"(a), "l"(b)); return d;
}
__device__ __forceinline__ uint64_t pack2(float x, float y) {
    uint64_t r; asm("mov.b64 %0, {%1, %2};" : "=l"(r) : "f"(x), "f"(y)); return r;
}
__device__ __forceinline__ void unpack2(float& x, float& y, uint64_t a) {
    asm("mov.b64 {%0, %1}, %2;" : "=f"(x), "=f"(y) : "l"(a));
}
// cp.async 16B
__device__ __forceinline__ void cp16(void* dst, const void* src) {
    unsigned u = (unsigned)__cvta_generic_to_shared(dst);
    asm volatile("cp.async.cg.shared.global [%0], [%1], 16;" :: "r"(u), "l"(src));
}

// ---------------- Kernel D (fused): masks -> W (registers->smem) -> sums -----
// grid (SPLIT, CSPLIT, B), block 256.
// Prologue (BARRIER-FREE): thread (x = tid&63, yy = tid>>6) reads its own 8x8
// mask window and reduces it entirely in registers:
//   per row: 8-bit SIMD one-hot fields in 3 u64 (shift + 3-way predicated add),
//   then PRMT-expand to 16-bit lanes and 12 IMAD into 12 u32 accumulators.
// Exact integers (lane max 1024 < 2^16) -> bit-identical W. Mainloop: feats
// double-buffered via cp.async; warp-uniform broadcast W reads; fma.rn.f32x2.
extern "C" __global__ void __launch_bounds__(256, 2) kernD(
        const float* __restrict__ feats, const int* __restrict__ masks) {
    extern __shared__ unsigned char smem[];
    uint64_t* Ws = (uint64_t*)smem;                 // [K][SRANGE]
    float*    Fs = (float*)(smem + FS_OFF);         // [2][CB*FSTR]
    uint16_t* Cs = (uint16_t*)(smem + CS_OFF);      // [4][K][68]

    int split = blockIdx.x, cb = blockIdx.y, b = blockIdx.z;
    int tid = threadIdx.x, warp = tid >> 5, lane = tid & 31;
    int g = warp & 1, sub = warp >> 1;              // 2 cgroups x 4 s-subranges

    // ---- Prologue: direct 8x8 window, all-register ----
    {
        int x = tid & 63, yy = tid >> 6;
        int y = split * 4 + yy;

        unsigned wy8[8], wx8[8];
        int po[4];
        #pragma unroll
        for (int d = 0; d < 8; d++) {
            int Y = 4 * y - 2 + d;
            wy8[d] = (Y < 0 || Y >= HO) ? 0u : (unsigned)bil_w8(Y, y);
            int X = 4 * x - 2 + d;
            wx8[d] = (X < 0 || X >= HO) ? 0u : (unsigned)bil_w8(X, x);
        }
        #pragma unroll
        for (int j = 0; j < 4; j++)
            po[j] = min(max(4 * x - 2 + 2 * j, 0), HO - 2) >> 1;  // int2 index

        unsigned acc12[12];
        #pragma unroll
        for (int j = 0; j < 12; j++) acc12[j] = 0u;

        #pragma unroll
        for (int dy = 0; dy < 8; dy++) {
            unsigned wy = wy8[dy];
            if (wy == 0) continue;                  // warp-uniform (boundary rows)
            int Y = 4 * y - 2 + dy;
            const int2* row = (const int2*)(masks + ((size_t)b * HO + Y) * HO);
            uint64_t r0 = 0, r1 = 0, r2 = 0;
            #pragma unroll
            for (int j = 0; j < 4; j++) {
                int2 p = row[po[j]];
                #pragma unroll
                for (int h = 0; h < 2; h++) {
                    int lbl = h ? p.y : p.x;
                    unsigned wx = wx8[2 * j + h];
                    uint64_t a = (uint64_t)wx << ((lbl & 7) * 8);
                    a = ((unsigned)lbl < (unsigned)K) ? a : 0ull;
                    int s3 = lbl >> 3;
                    r0 += (s3 == 0) ? a : 0ull;
                    r1 += (s3 == 1) ? a : 0ull;
                    r2 += (s3 == 2) ? a : 0ull;
                }
            }
            // expand 8-bit fields to 16-bit lanes, scale by wy, accumulate
            unsigned v0 = (unsigned)r0, v1 = (unsigned)(r0 >> 32);
            unsigned v2 = (unsigned)r1, v3 = (unsigned)(r1 >> 32);
            unsigned v4 = (unsigned)r2, v5 = (unsigned)(r2 >> 32);
            acc12[0]  += __byte_perm(v0, 0, 0x4140) * wy;
            acc12[1]  += __byte_perm(v0, 0, 0x4342) * wy;
            acc12[2]  += __byte_perm(v1, 0, 0x4140) * wy;
            acc12[3]  += __byte_perm(v1, 0, 0x4342) * wy;
            acc12[4]  += __byte_perm(v2, 0, 0x4140) * wy;
            acc12[5]  += __byte_perm(v2, 0, 0x4342) * wy;
            acc12[6]  += __byte_perm(v3, 0, 0x4140) * wy;
            acc12[7]  += __byte_perm(v3, 0, 0x4342) * wy;
            acc12[8]  += __byte_perm(v4, 0, 0x4140) * wy;
            acc12[9]  += __byte_perm(v4, 0, 0x4342) * wy;
            acc12[10] += __byte_perm(v5, 0, 0x4140) * wy;
            acc12[11] += __byte_perm(v5, 0, 0x4342) * wy;
        }

        // emit: W dup pairs into resident smem + Cs count entries
        int sl = yy * HIN + x;
        #pragma unroll
        for (int k = 0; k < K; k++) {
            unsigned val = (acc12[k >> 1] >> ((k & 1) * 16)) & 0xFFFFu;
            float f = (float)val * (1.0f / 64.0f);
            Ws[k * SRANGE + sl] = pack2(f, f);
            Cs[(yy * K + k) * 68 + x] = (uint16_t)val;
        }
    }
    __syncthreads();   // Ws/Cs valid

    const float* Fg = feats + ((size_t)b * C + cb * CB) * S;
    const int sbase0 = split * SRANGE;

    #define STAGE(BUF, SB) do {                                                   \
        for (int i = tid; i < CB * SCH / 4; i += 256) {                           \
            int c = i >> 4, j4 = i & 15;                                          \
            cp16(&Fs[(BUF) * CB * FSTR + c * FSTR + j4 * 4],                      \
                 Fg + (size_t)c * S + (SB) + j4 * 4);                             \
        }                                                                         \
        asm volatile("cp.async.commit_group;");                                   \
    } while (0)

    STAGE(0, sbase0);   // targets buf0; Cs (aliasing buf1) still live

    // exact integer row counts (cb==0 only; concurrent with stage 0)
    if (cb == 0 && tid < 4 * K) {
        int yy = tid & 3, k = tid >> 2;
        const uint16_t* cp = &Cs[(yy * K + k) * 68];
        unsigned t = 0;
        #pragma unroll 16
        for (int xx = 0; xx < HIN; xx++) t += (unsigned)cp[xx];
        g_rowcnt[(b * K + k) * HIN + split * 4 + yy] = t;
    }
    __syncthreads();   // Cs dead; buf1 free for prefetch

    uint64_t acc[K];
    #pragma unroll
    for (int k = 0; k < K; k++) acc[k] = 0ull;

    #pragma unroll 1
    for (int chunk = 0; chunk < NCH; chunk++) {
        if (chunk + 1 < NCH) {
            STAGE((chunk + 1) & 1, sbase0 + (chunk + 1) * SCH);
            asm volatile("cp.async.wait_group 1;");
        } else {
            asm volatile("cp.async.wait_group 0;");
        }
        __syncthreads();

        const float* fA = &Fs[(chunk & 1) * CB * FSTR + (g * 32 + lane) * FSTR];
        const float* fB = fA + 64 * FSTR;
        const uint64_t* Wb = &Ws[chunk * SCH];
        int sb = sub * 16;
        #pragma unroll
        for (int i = 0; i < 16; i += 4) {
            int s = sb + i;
            float4 va = *(const float4*)&fA[s];
            float4 vb = *(const float4*)&fB[s];
            uint64_t p0 = pack2(va.x, vb.x);
            uint64_t p1 = pack2(va.y, vb.y);
            uint64_t p2 = pack2(va.z, vb.z);
            uint64_t p3 = pack2(va.w, vb.w);
            #pragma unroll
            for (int k = 0; k < K; k++) {
                ulonglong2 w01 = *(const ulonglong2*)&Wb[k * SRANGE + s];       // broadcast
                ulonglong2 w23 = *(const ulonglong2*)&Wb[k * SRANGE + s + 2];   // broadcast
                fma2(acc[k], p0, w01.x);
                fma2(acc[k], p1, w01.y);
                fma2(acc[k], p2, w23.x);
                fma2(acc[k], p3, w23.y);
            }
        }
        __syncthreads();   // protect feats buffer reuse by next prefetch
    }
    #undef STAGE

    // reduce 4 s-subrange warps per channel-group via smem (Ws region, now dead)
    uint64_t* red = (uint64_t*)smem;   // 2g x 2 x K x 32 u64 = 21504 B
    if (sub >= 2) {
        #pragma unroll
        for (int k = 0; k < K; k++) red[((g * 2 + (sub - 2)) * K + k) * 32 + lane] = acc[k];
    }
    __syncthreads();
    if (sub < 2) {
        #pragma unroll
        for (int k = 0; k < K; k++) acc[k] = add2(acc[k], red[((g * 2 + sub) * K + k) * 32 + lane]);
    }
    __syncthreads();
    if (sub == 1) {
        #pragma unroll
        for (int k = 0; k < K; k++) red[(g * K + k) * 32 + lane] = acc[k];
    }
    __syncthreads();
    if (sub == 0) {
        float* outp = &g_sums[(((size_t)split * B + b) * K) * C];
        int cg = cb * CB + g * 32 + lane;
        #pragma unroll
        for (int k = 0; k < K; k++) {
            uint64_t t = add2(acc[k], red[(g * K + k) * 32 + lane]);
            float ax, ay;
            unpack2(ax, ay, t);
            outp[k * C + cg]      = ax;
            outp[k * C + cg + 64] = ay;
        }
    }
}

// ---------------- Kernel E: finalize prototypes ------------------------------
// grid (K, 8), block 256 = 8 warps (one per b) x 32 lanes (one channel each).
// 168 blocks of coalesced scalar loads; exact counts from rowcnt; no atomics.
__global__ void kernE(float* __restrict__ out) {
    int k = blockIdx.x, cg = blockIdx.y;
    int tid = threadIdx.x, b = tid >> 5, lane = tid & 31;
    int c = cg * 32 + lane;

    float v = 0.f;
    #pragma unroll
    for (int sp = 0; sp < SPLIT; sp++)
        v += g_sums[((sp * B + b) * K + k) * C + c];

    // exact count for (b,k): warp-reduce 64 row counts (result in all lanes)
    const unsigned* rc = &g_rowcnt[(b * K + k) * HIN];
    unsigned cr = rc[lane] + rc[lane + 32];
    #pragma unroll
    for (int o = 16; o > 0; o >>= 1) cr += __shfl_xor_sync(0xFFFFFFFFu, cr, o);
    v *= 1.0f / ((float)cr * (1.0f / 64.0f) + EPSF);

    __shared__ float red[B][32];
    red[b][lane] = v;
    __syncthreads();
    if (b == 0) {
        float a = red[0][lane];
        #pragma unroll
        for (int w = 1; w < B; w++) a += red[w][lane];
        out[k * C + c] = a * (1.0f / (float)B);
    }
}

// ---------------- launch -----------------------------------------------------
extern "C" void kernel_launch(void* const* d_in, const int* in_sizes, int n_in,
                              void* d_out, int out_size) {
    const float* feats = (const float*)d_in[0];   // [8,256,64,64]
    const int*   masks = (const int*)d_in[1];     // [8,256,256]
    float*       out   = (float*)d_out;           // [21,256]

    cudaFuncSetAttribute(kernD, cudaFuncAttributeMaxDynamicSharedMemorySize, SMEM_D);

    kernD<<<dim3(SPLIT, CSPLIT, B), 256, SMEM_D>>>(feats, masks);
    kernE<<<dim3(K, 8), 256>>>(out);
}